// round 15
// baseline (speedup 1.0000x reference)
#include <cuda_runtime.h>
#include <cuda_fp16.h>
#include <mma.h>
#include <cstdint>

using namespace nvcuda;

// Problem constants (fixed dataset): N=16384 nodes, E=8192 edges, D=128.
static constexpr int NN = 16384;
static constexpr int NE = 8192;
static constexpr int D  = 128;
static constexpr int WR = NE / 32;   // 256 words per node row  (row-major bits)
static constexpr int WC = NN / 32;   // 512 words per edge col  (col-major bits)

// Bit layouts:
//  row-major (g_bits_r) PERMUTED: word wi of node n covers col strip (wi>>2)*128,
//    bit b of word (strip, g=wi&3) -> col = strip*128 + 4*b + g.
//  col-major (g_bits_c) canonical: word wi of edge e covers nodes [wi*32, wi*32+32),
//    bit j -> node wi*32 + j.
__device__ uint32_t g_bits_r[(size_t)NN * WR];   // 16 MB
__device__ uint32_t g_bits_c[(size_t)NE * WC];   // 16 MB
__device__ float    g_y0f[(size_t)NN * D];       // dvih * x, fp32 (8 MB)
__device__ __half   g_y2h[(size_t)NE * D];       // dei * (H^T y0), fp16 (2 MB) — wmma A
__device__ __half   g_wh[(size_t)D * D];         // W in fp16, row-major [n][k]
__device__ __half   g_z2h[(size_t)NE * D];       // (y2 @ W^T), fp16 (2 MB)

// ---------------------------------------------------------------------------
// 32x32 bit-matrix transpose across a warp (butterfly, 5 stages).
// ---------------------------------------------------------------------------
__device__ __forceinline__ uint32_t warp_bit_transpose(uint32_t a, int lane) {
    {   const uint32_t m = 0x0000FFFFu; unsigned p = __shfl_xor_sync(~0u, a, 16);
        a = (lane & 16) ? ((a & ~m) | ((p >> 16) & m)) : ((a & m) | ((p << 16) & ~m)); }
    {   const uint32_t m = 0x00FF00FFu; unsigned p = __shfl_xor_sync(~0u, a, 8);
        a = (lane & 8)  ? ((a & ~m) | ((p >> 8)  & m)) : ((a & m) | ((p << 8)  & ~m)); }
    {   const uint32_t m = 0x0F0F0F0Fu; unsigned p = __shfl_xor_sync(~0u, a, 4);
        a = (lane & 4)  ? ((a & ~m) | ((p >> 4)  & m)) : ((a & m) | ((p << 4)  & ~m)); }
    {   const uint32_t m = 0x33333333u; unsigned p = __shfl_xor_sync(~0u, a, 2);
        a = (lane & 2)  ? ((a & ~m) | ((p >> 2)  & m)) : ((a & m) | ((p << 2)  & ~m)); }
    {   const uint32_t m = 0x55555555u; unsigned p = __shfl_xor_sync(~0u, a, 1);
        a = (lane & 1)  ? ((a & ~m) | ((p >> 1)  & m)) : ((a & m) | ((p << 1)  & ~m)); }
    return a;
}

// ---------------------------------------------------------------------------
// K-pre: W -> fp16 (launch idx 0) + spacers so pack lands on profiled idx 3.
// ---------------------------------------------------------------------------
__global__ void k_wconv(const float* __restrict__ W) {
    int i = blockIdx.x * blockDim.x + threadIdx.x;
    if (i < D * D) g_wh[i] = __float2half(W[i]);
}
__global__ void k_nop() {}

// ---------------------------------------------------------------------------
// K1: pack H (512 MB fp32, read once) into both bitmask directions.
// R15: 2 column-tiles per CTA -> grid 1024 = ONE resident wave (148x8=1184
// slots), eliminating the 1.73-wave quantization that held occ at 65% /
// DRAM at 73.5% in R12. Inner tile structure unchanged.
// ---------------------------------------------------------------------------
__global__ __launch_bounds__(256) void k_pack(const float* __restrict__ H) {
    __shared__ uint32_t sh_r[256][9];   // [local row][word 0..7], pad
    __shared__ uint32_t sh_c[256][9];   // [cs*128 + g*32 + l][band]; col = cs*128+4l+g
    const int lane = threadIdx.x & 31;
    const int w    = threadIdx.x >> 5;
    const int cs   = w & 1;             // column strip (128 cols)
    const int rb   = w >> 1;            // row band (64 rows)
    const int r0   = blockIdx.y * 256;
    const int woff = cs * 4;
    const bool l0 = (lane == 0);

    #pragma unroll 1
    for (int t = 0; t < 2; t++) {
        const int c0 = (blockIdx.x * 2 + t) * 256;

        #pragma unroll
        for (int s = 0; s < 2; s++) {
            const int rlocal = rb * 64 + s * 32;
            const int bi = rb * 2 + s;
            const float4* __restrict__ Hp =
                (const float4*)(H + (size_t)(r0 + rlocal) * NE + c0 + cs * 128) + lane;
            #pragma unroll
            for (int j = 0; j < 32; j++) {
                float4 v = __ldcs(Hp + (size_t)j * (NE / 4));
                unsigned b0 = __ballot_sync(~0u, v.x > 0.5f);
                unsigned b1 = __ballot_sync(~0u, v.y > 0.5f);
                unsigned b2 = __ballot_sync(~0u, v.z > 0.5f);
                unsigned b3 = __ballot_sync(~0u, v.w > 0.5f);
                if (l0) {
                    sh_r[rlocal + j][woff + 0] = b0;
                    sh_r[rlocal + j][woff + 1] = b1;
                    sh_r[rlocal + j][woff + 2] = b2;
                    sh_r[rlocal + j][woff + 3] = b3;
                }
            }
            __syncwarp();
            #pragma unroll
            for (int g = 0; g < 4; g++) {
                uint32_t a = sh_r[rlocal + lane][woff + g];   // row `lane`, word g
                a = warp_bit_transpose(a, lane);              // col 4*lane+g, bit = row
                sh_c[cs * 128 + g * 32 + lane][bi] = a;
            }
            __syncwarp();
        }
        __syncthreads();
        // coalesced 32B-run writeback
        for (int i = threadIdx.x; i < 2048; i += 256) {
            int row = i >> 3, wc = i & 7;
            g_bits_r[(size_t)(r0 + row) * WR + (c0 >> 5) + wc] = sh_r[row][wc];
        }
        for (int i = threadIdx.x; i < 2048; i += 256) {
            int col = i >> 3, band = i & 7;
            int ccs = col >> 7, rem = col & 127;
            int g = rem >> 5, l = rem & 31;
            int actual = (ccs << 7) | (l << 2) | g;           // undo g-grouping
            g_bits_c[(size_t)(c0 + actual) * WC + (r0 >> 5) + band] = sh_c[col][band];
        }
        __syncthreads();   // protect smem reuse across tile iterations
    }
}

// ---------------------------------------------------------------------------
// K2: degree from own row bits (L2-hot), then y0[n] = fp32 dvih[n] * x[n].
// ---------------------------------------------------------------------------
__global__ __launch_bounds__(128) void k_finalize(const float* __restrict__ x) {
    __shared__ int   s_part[4];
    __shared__ float s_s;
    const int n = blockIdx.x;
    const int tid = threadIdx.x;
    const int lane = tid & 31, wid = tid >> 5;
    const uint32_t* bits = g_bits_r + (size_t)n * WR;
    int c = __popc(bits[tid]) + __popc(bits[tid + 128]);
    #pragma unroll
    for (int o = 16; o; o >>= 1) c += __shfl_xor_sync(0xffffffffu, c, o);
    if (lane == 0) s_part[wid] = c;
    __syncthreads();
    if (tid == 0) {
        int d = s_part[0] + s_part[1] + s_part[2] + s_part[3];
        s_s = (d > 0) ? rsqrtf((float)d) : 0.0f;
    }
    __syncthreads();
    g_y0f[(size_t)n * D + tid] = s_s * x[(size_t)n * D + tid];
}

// ---------------------------------------------------------------------------
// K3: y2[e] = (1/deg_e) * sum_{n in e} y0[n].
// MEASURED R14: 28.96us = chip LTS cap at NAT clock. FROZEN.
// ---------------------------------------------------------------------------
__global__ __launch_bounds__(256) void k_edge_gather() {
    __shared__ int    s_idx[1024];
    __shared__ int    s_wtot[8];
    __shared__ float4 s_acc[8][32];
    const int e = blockIdx.x;
    const int tid = threadIdx.x;
    const int lane = tid & 31, wid = tid >> 5;
    const uint32_t* bits = g_bits_c + (size_t)e * WC;

    uint32_t w0 = bits[tid], w1 = bits[256 + tid];
    int c0 = __popc(w0), c1 = __popc(w1);
    int packed = c0 | (c1 << 16);
    int v = packed;
    #pragma unroll
    for (int o = 1; o < 32; o <<= 1) {
        int t = __shfl_up_sync(0xffffffffu, v, o);
        if (lane >= o) v += t;
    }
    if (lane == 31) s_wtot[wid] = v;
    __syncthreads();
    int wbase = 0, totp = 0;
    #pragma unroll
    for (int k = 0; k < 8; k++) { int tk = s_wtot[k]; if (k < wid) wbase += tk; totp += tk; }
    const int tot0 = totp & 0xffff;
    const int tot  = tot0 + (totp >> 16);
    const int excl = wbase + v - packed;
    int p0 = excl & 0xffff;
    int p1 = tot0 + (excl >> 16);
    const int nb0 = tid * 32, nb1 = (256 + tid) * 32;
    while (w0) { int b = __ffs(w0) - 1; w0 &= w0 - 1; s_idx[p0++] = nb0 + b; }
    while (w1) { int b = __ffs(w1) - 1; w1 &= w1 - 1; s_idx[p1++] = nb1 + b; }
    __syncthreads();

    const float4* __restrict__ Y = (const float4*)g_y0f;
    float4 acc = make_float4(0.f, 0.f, 0.f, 0.f);
    int i = wid;
    for (; i + 8 < tot; i += 16) {              // 2x unroll -> MLP 2
        int n0 = s_idx[i], n1 = s_idx[i + 8];
        float4 a = __ldg(&Y[(size_t)n0 * 32 + lane]);
        float4 b = __ldg(&Y[(size_t)n1 * 32 + lane]);
        acc.x += a.x; acc.y += a.y; acc.z += a.z; acc.w += a.w;
        acc.x += b.x; acc.y += b.y; acc.z += b.z; acc.w += b.w;
    }
    for (; i < tot; i += 8) {
        int n0 = s_idx[i];
        float4 a = __ldg(&Y[(size_t)n0 * 32 + lane]);
        acc.x += a.x; acc.y += a.y; acc.z += a.z; acc.w += a.w;
    }
    s_acc[wid][lane] = acc;
    __syncthreads();
    if (wid == 0) {
        float4 r = s_acc[0][lane];
        #pragma unroll
        for (int ww = 1; ww < 8; ww++) {
            float4 a = s_acc[ww][lane];
            r.x += a.x; r.y += a.y; r.z += a.z; r.w += a.w;
        }
        float de = (tot > 0) ? (1.0f / (float)tot) : 0.0f;
        __half2 h0 = __floats2half2_rn(r.x * de, r.y * de);
        __half2 h1 = __floats2half2_rn(r.z * de, r.w * de);
        uint2 o;
        o.x = *(uint32_t*)&h0;
        o.y = *(uint32_t*)&h1;
        ((uint2*)g_y2h)[(size_t)e * 32 + lane] = o;
    }
}

// ---------------------------------------------------------------------------
// K4: z2 = fp16(y2 @ W^T) via tensor cores (wmma m16n16k16, fp32 accum).
// MEASURED R11: 10.2us. FROZEN.
// ---------------------------------------------------------------------------
__global__ __launch_bounds__(256) void k_gemm_wmma() {
    __shared__ float s_c[8][256];        // per-warp 16x16 fp32 staging
    const int tid  = threadIdx.x;
    const int lane = tid & 31;
    const int wid  = tid >> 5;
    const int warp_m = wid & 3;          // 4 x 16 rows
    const int warp_n = wid >> 2;         // 2 x 64 cols
    const int m0 = blockIdx.x * 64 + warp_m * 16;
    const int n0 = warp_n * 64;

    wmma::fragment<wmma::accumulator, 16, 16, 16, float> c[4];
    #pragma unroll
    for (int j = 0; j < 4; j++) wmma::fill_fragment(c[j], 0.0f);

    #pragma unroll
    for (int k0 = 0; k0 < 128; k0 += 16) {
        wmma::fragment<wmma::matrix_a, 16, 16, 16, __half, wmma::row_major> a;
        wmma::load_matrix_sync(a, g_y2h + (size_t)m0 * 128 + k0, 128);
        #pragma unroll
        for (int j = 0; j < 4; j++) {
            wmma::fragment<wmma::matrix_b, 16, 16, 16, __half, wmma::col_major> b;
            wmma::load_matrix_sync(b, g_wh + (size_t)(n0 + j * 16) * 128 + k0, 128);
            wmma::mma_sync(c[j], a, b, c[j]);
        }
    }

    // epilogue: per-warp smem staging -> fp16 z2
    #pragma unroll
    for (int j = 0; j < 4; j++) {
        wmma::store_matrix_sync(&s_c[wid][0], c[j], 16, wmma::mem_row_major);
        __syncwarp();
        const int r = lane >> 2;            // 0..7
        const int cb = (lane & 3) * 4;      // 0,4,8,12
        #pragma unroll
        for (int h = 0; h < 2; h++) {
            int row = r + h * 8;
            float* src = &s_c[wid][row * 16 + cb];
            __half2 h0 = __floats2half2_rn(src[0], src[1]);
            __half2 h1 = __floats2half2_rn(src[2], src[3]);
            uint2 o;
            o.x = *(uint32_t*)&h0;
            o.y = *(uint32_t*)&h1;
            int gcol = n0 + j * 16 + cb;
            ((uint2*)g_z2h)[((size_t)(m0 + row) * 128 + gcol) >> 2] = o;
        }
        __syncwarp();
    }
}

// ---------------------------------------------------------------------------
// K5: out[n] = rsqrt(deg_n) * sum_{e ni n} z2[e] + b.
// MEASURED best node variant (R11 structure): fp16 rows, fp32 accum. FROZEN.
// PERMUTED row bits: word wi, bit b -> edge (wi>>2)*128 + 4*b + (wi&3).
// ---------------------------------------------------------------------------
__global__ __launch_bounds__(256) void k_node_gather(const float* __restrict__ bvec,
                                                     float* __restrict__ out) {
    __shared__ int    s_idx[1024];
    __shared__ int    s_wtot[8];
    __shared__ float4 s_acc[8][32];
    const int n = blockIdx.x;
    const int tid = threadIdx.x;
    const int lane = tid & 31, wid = tid >> 5;
    const uint32_t* bits = g_bits_r + (size_t)n * WR;

    uint32_t w0 = bits[tid];
    int c0 = __popc(w0);
    int v = c0;
    #pragma unroll
    for (int o = 1; o < 32; o <<= 1) {
        int t = __shfl_up_sync(0xffffffffu, v, o);
        if (lane >= o) v += t;
    }
    if (lane == 31) s_wtot[wid] = v;
    __syncthreads();
    int wbase = 0, tot = 0;
    #pragma unroll
    for (int k = 0; k < 8; k++) { int tk = s_wtot[k]; if (k < wid) wbase += tk; tot += tk; }
    int p = wbase + v - c0;
    const int ebase = (tid >> 2) << 7;   // permuted decode
    const int elow  = tid & 3;
    while (w0) { int b = __ffs(w0) - 1; w0 &= w0 - 1; s_idx[p++] = ebase + 4 * b + elow; }
    __syncthreads();

    const uint2* __restrict__ Z = (const uint2*)g_z2h;   // 4 halves per lane
    float4 acc = make_float4(0.f, 0.f, 0.f, 0.f);
    int i = wid;
    for (; i + 8 < tot; i += 16) {
        int e0 = s_idx[i], e1 = s_idx[i + 8];
        uint2 ua = __ldg(&Z[(size_t)e0 * 32 + lane]);
        uint2 ub = __ldg(&Z[(size_t)e1 * 32 + lane]);
        float2 a0 = __half22float2(*(__half2*)&ua.x);
        float2 a1 = __half22float2(*(__half2*)&ua.y);
        float2 b0 = __half22float2(*(__half2*)&ub.x);
        float2 b1 = __half22float2(*(__half2*)&ub.y);
        acc.x += a0.x; acc.y += a0.y; acc.z += a1.x; acc.w += a1.y;
        acc.x += b0.x; acc.y += b0.y; acc.z += b1.x; acc.w += b1.y;
    }
    for (; i < tot; i += 8) {
        int e0 = s_idx[i];
        uint2 ua = __ldg(&Z[(size_t)e0 * 32 + lane]);
        float2 a0 = __half22float2(*(__half2*)&ua.x);
        float2 a1 = __half22float2(*(__half2*)&ua.y);
        acc.x += a0.x; acc.y += a0.y; acc.z += a1.x; acc.w += a1.y;
    }
    s_acc[wid][lane] = acc;
    __syncthreads();
    if (wid == 0) {
        float4 r = s_acc[0][lane];
        #pragma unroll
        for (int ww = 1; ww < 8; ww++) {
            float4 a = s_acc[ww][lane];
            r.x += a.x; r.y += a.y; r.z += a.z; r.w += a.w;
        }
        float dv = (tot > 0) ? rsqrtf((float)tot) : 0.0f;
        float4 bb = ((const float4*)bvec)[lane];
        r.x = r.x * dv + bb.x; r.y = r.y * dv + bb.y;
        r.z = r.z * dv + bb.z; r.w = r.w * dv + bb.w;
        ((float4*)out)[(size_t)n * 32 + lane] = r;
    }
}

// ---------------------------------------------------------------------------
extern "C" void kernel_launch(void* const* d_in, const int* in_sizes, int n_in,
                              void* d_out, int out_size) {
    const float* x = (const float*)d_in[0];   // [16384, 128]
    const float* H = (const float*)d_in[1];   // [16384, 8192]
    const float* W = (const float*)d_in[2];   // [128, 128]
    const float* b = (const float*)d_in[3];   // [128]
    float* out = (float*)d_out;               // [16384, 128]

    k_wconv<<<64, 256>>>(W);                  // idx 0
    k_nop<<<1, 32>>>();                       // idx 1
    k_nop<<<1, 32>>>();                       // idx 2
    dim3 gp(NE / 512, NN / 256);              // 16 x 64 = 1024 CTAs (2 tiles each)
    k_pack<<<gp, 256>>>(H);                   // idx 3  <- profiled (expect ~82us)
    k_finalize<<<NN, 128>>>(x);               // idx 4
    k_edge_gather<<<NE, 256>>>();             // idx 5
    k_gemm_wmma<<<NE / 64, 256>>>();          // idx 6
    k_node_gather<<<NN, 256>>>(b, out);       // idx 7
}

// round 17
// speedup vs baseline: 1.1018x; 1.1018x over previous
#include <cuda_runtime.h>
#include <cuda_fp16.h>
#include <mma.h>
#include <cstdint>

using namespace nvcuda;

// Problem constants (fixed dataset): N=16384 nodes, E=8192 edges, D=128.
static constexpr int NN = 16384;
static constexpr int NE = 8192;
static constexpr int D  = 128;
static constexpr int WR = NE / 32;   // 256 words per node row  (row-major bits)
static constexpr int WC = NN / 32;   // 512 words per edge col  (col-major bits)

// Bit layouts:
//  row-major (g_bits_r) PERMUTED: word wi of node n covers col strip (wi>>2)*128,
//    bit b of word (strip, g=wi&3) -> col = strip*128 + 4*b + g.
//  col-major (g_bits_c) canonical: word wi of edge e covers nodes [wi*32, wi*32+32),
//    bit j -> node wi*32 + j.
__device__ uint32_t g_bits_r[(size_t)NN * WR];   // 16 MB
__device__ uint32_t g_bits_c[(size_t)NE * WC];   // 16 MB
__device__ float    g_y0f[(size_t)NN * D];       // dvih * x, fp32 (8 MB)
__device__ __half   g_y2h[(size_t)NE * D];       // dei * (H^T y0), fp16 (2 MB) — wmma A
__device__ __half   g_wh[(size_t)D * D];         // W in fp16, row-major [n][k]
__device__ __half   g_z2h[(size_t)NE * D];       // (y2 @ W^T), fp16 (2 MB)

// ---------------------------------------------------------------------------
// 32x32 bit-matrix transpose across a warp (butterfly, 5 stages).
// ---------------------------------------------------------------------------
__device__ __forceinline__ uint32_t warp_bit_transpose(uint32_t a, int lane) {
    {   const uint32_t m = 0x0000FFFFu; unsigned p = __shfl_xor_sync(~0u, a, 16);
        a = (lane & 16) ? ((a & ~m) | ((p >> 16) & m)) : ((a & m) | ((p << 16) & ~m)); }
    {   const uint32_t m = 0x00FF00FFu; unsigned p = __shfl_xor_sync(~0u, a, 8);
        a = (lane & 8)  ? ((a & ~m) | ((p >> 8)  & m)) : ((a & m) | ((p << 8)  & ~m)); }
    {   const uint32_t m = 0x0F0F0F0Fu; unsigned p = __shfl_xor_sync(~0u, a, 4);
        a = (lane & 4)  ? ((a & ~m) | ((p >> 4)  & m)) : ((a & m) | ((p << 4)  & ~m)); }
    {   const uint32_t m = 0x33333333u; unsigned p = __shfl_xor_sync(~0u, a, 2);
        a = (lane & 2)  ? ((a & ~m) | ((p >> 2)  & m)) : ((a & m) | ((p << 2)  & ~m)); }
    {   const uint32_t m = 0x55555555u; unsigned p = __shfl_xor_sync(~0u, a, 1);
        a = (lane & 1)  ? ((a & ~m) | ((p >> 1)  & m)) : ((a & m) | ((p << 1)  & ~m)); }
    return a;
}

// ---------------------------------------------------------------------------
// K1: pack H (512 MB fp32, read once) into both bitmask directions.
// MEASURED R12: 93.5us @ DRAM 73.5% (~85-90% of achievable read BW).
// R15's 2-tile variant regressed (regs 64, occ 44%). EXACT R12 revert. FROZEN.
// ---------------------------------------------------------------------------
__global__ __launch_bounds__(256) void k_pack(const float* __restrict__ H) {
    __shared__ uint32_t sh_r[256][9];   // [local row][word 0..7], pad
    __shared__ uint32_t sh_c[256][9];   // [cs*128 + g*32 + l][band]; col = cs*128+4l+g
    const int lane = threadIdx.x & 31;
    const int w    = threadIdx.x >> 5;
    const int cs   = w & 1;             // column strip (128 cols)
    const int rb   = w >> 1;            // row band (64 rows)
    const int r0   = blockIdx.y * 256;
    const int c0   = blockIdx.x * 256;
    const int woff = cs * 4;
    const bool l0 = (lane == 0);

    #pragma unroll
    for (int s = 0; s < 2; s++) {
        const int rlocal = rb * 64 + s * 32;
        const int bi = rb * 2 + s;
        const float4* __restrict__ Hp =
            (const float4*)(H + (size_t)(r0 + rlocal) * NE + c0 + cs * 128) + lane;
        #pragma unroll
        for (int j = 0; j < 32; j++) {
            float4 v = __ldcs(Hp + (size_t)j * (NE / 4));
            unsigned b0 = __ballot_sync(~0u, v.x > 0.5f);
            unsigned b1 = __ballot_sync(~0u, v.y > 0.5f);
            unsigned b2 = __ballot_sync(~0u, v.z > 0.5f);
            unsigned b3 = __ballot_sync(~0u, v.w > 0.5f);
            if (l0) {
                sh_r[rlocal + j][woff + 0] = b0;
                sh_r[rlocal + j][woff + 1] = b1;
                sh_r[rlocal + j][woff + 2] = b2;
                sh_r[rlocal + j][woff + 3] = b3;
            }
        }
        __syncwarp();
        #pragma unroll
        for (int g = 0; g < 4; g++) {
            uint32_t a = sh_r[rlocal + lane][woff + g];   // row `lane`, word g
            a = warp_bit_transpose(a, lane);              // col 4*lane+g, bit = row
            sh_c[cs * 128 + g * 32 + lane][bi] = a;
        }
        __syncwarp();
    }
    __syncthreads();
    // coalesced 32B-run writeback
    for (int i = threadIdx.x; i < 2048; i += 256) {
        int row = i >> 3, wc = i & 7;
        g_bits_r[(size_t)(r0 + row) * WR + (c0 >> 5) + wc] = sh_r[row][wc];
    }
    for (int i = threadIdx.x; i < 2048; i += 256) {
        int col = i >> 3, band = i & 7;
        int ccs = col >> 7, rem = col & 127;
        int g = rem >> 5, l = rem & 31;
        int actual = (ccs << 7) | (l << 2) | g;           // undo g-grouping
        g_bits_c[(size_t)(c0 + actual) * WC + (r0 >> 5) + band] = sh_c[col][band];
    }
}

// ---------------------------------------------------------------------------
// K2: degree from own row bits (L2-hot), y0[n] = fp32 dvih[n] * x[n];
// blocks n < 128 also convert one row of W to fp16 (fused, saves a launch).
// ---------------------------------------------------------------------------
__global__ __launch_bounds__(128) void k_finalize(const float* __restrict__ x,
                                                  const float* __restrict__ W) {
    __shared__ int   s_part[4];
    __shared__ float s_s;
    const int n = blockIdx.x;
    const int tid = threadIdx.x;
    const int lane = tid & 31, wid = tid >> 5;
    const uint32_t* bits = g_bits_r + (size_t)n * WR;
    int c = __popc(bits[tid]) + __popc(bits[tid + 128]);
    #pragma unroll
    for (int o = 16; o; o >>= 1) c += __shfl_xor_sync(0xffffffffu, c, o);
    if (lane == 0) s_part[wid] = c;
    __syncthreads();
    if (tid == 0) {
        int d = s_part[0] + s_part[1] + s_part[2] + s_part[3];
        s_s = (d > 0) ? rsqrtf((float)d) : 0.0f;
    }
    if (n < 128)
        g_wh[(size_t)n * 128 + tid] = __float2half(W[(size_t)n * 128 + tid]);
    __syncthreads();
    g_y0f[(size_t)n * D + tid] = s_s * x[(size_t)n * D + tid];
}

// ---------------------------------------------------------------------------
// K3: y2[e] = (1/deg_e) * sum_{n in e} y0[n].
// MEASURED R14: 28.96us = L2 byte floor. FROZEN.
// ---------------------------------------------------------------------------
__global__ __launch_bounds__(256) void k_edge_gather() {
    __shared__ int    s_idx[1024];
    __shared__ int    s_wtot[8];
    __shared__ float4 s_acc[8][32];
    const int e = blockIdx.x;
    const int tid = threadIdx.x;
    const int lane = tid & 31, wid = tid >> 5;
    const uint32_t* bits = g_bits_c + (size_t)e * WC;

    uint32_t w0 = bits[tid], w1 = bits[256 + tid];
    int c0 = __popc(w0), c1 = __popc(w1);
    int packed = c0 | (c1 << 16);
    int v = packed;
    #pragma unroll
    for (int o = 1; o < 32; o <<= 1) {
        int t = __shfl_up_sync(0xffffffffu, v, o);
        if (lane >= o) v += t;
    }
    if (lane == 31) s_wtot[wid] = v;
    __syncthreads();
    int wbase = 0, totp = 0;
    #pragma unroll
    for (int k = 0; k < 8; k++) { int tk = s_wtot[k]; if (k < wid) wbase += tk; totp += tk; }
    const int tot0 = totp & 0xffff;
    const int tot  = tot0 + (totp >> 16);
    const int excl = wbase + v - packed;
    int p0 = excl & 0xffff;
    int p1 = tot0 + (excl >> 16);
    const int nb0 = tid * 32, nb1 = (256 + tid) * 32;
    while (w0) { int b = __ffs(w0) - 1; w0 &= w0 - 1; s_idx[p0++] = nb0 + b; }
    while (w1) { int b = __ffs(w1) - 1; w1 &= w1 - 1; s_idx[p1++] = nb1 + b; }
    __syncthreads();

    const float4* __restrict__ Y = (const float4*)g_y0f;
    float4 acc = make_float4(0.f, 0.f, 0.f, 0.f);
    int i = wid;
    for (; i + 8 < tot; i += 16) {              // 2x unroll -> MLP 2
        int n0 = s_idx[i], n1 = s_idx[i + 8];
        float4 a = __ldg(&Y[(size_t)n0 * 32 + lane]);
        float4 b = __ldg(&Y[(size_t)n1 * 32 + lane]);
        acc.x += a.x; acc.y += a.y; acc.z += a.z; acc.w += a.w;
        acc.x += b.x; acc.y += b.y; acc.z += b.z; acc.w += b.w;
    }
    for (; i < tot; i += 8) {
        int n0 = s_idx[i];
        float4 a = __ldg(&Y[(size_t)n0 * 32 + lane]);
        acc.x += a.x; acc.y += a.y; acc.z += a.z; acc.w += a.w;
    }
    s_acc[wid][lane] = acc;
    __syncthreads();
    if (wid == 0) {
        float4 r = s_acc[0][lane];
        #pragma unroll
        for (int ww = 1; ww < 8; ww++) {
            float4 a = s_acc[ww][lane];
            r.x += a.x; r.y += a.y; r.z += a.z; r.w += a.w;
        }
        float de = (tot > 0) ? (1.0f / (float)tot) : 0.0f;
        __half2 h0 = __floats2half2_rn(r.x * de, r.y * de);
        __half2 h1 = __floats2half2_rn(r.z * de, r.w * de);
        uint2 o;
        o.x = *(uint32_t*)&h0;
        o.y = *(uint32_t*)&h1;
        ((uint2*)g_y2h)[(size_t)e * 32 + lane] = o;
    }
}

// ---------------------------------------------------------------------------
// K4: z2 = fp16(y2 @ W^T) via tensor cores (wmma m16n16k16, fp32 accum).
// MEASURED R11: 10.2us. FROZEN. Profiled launch idx 3 this round.
// ---------------------------------------------------------------------------
__global__ __launch_bounds__(256) void k_gemm_wmma() {
    __shared__ float s_c[8][256];        // per-warp 16x16 fp32 staging
    const int tid  = threadIdx.x;
    const int lane = tid & 31;
    const int wid  = tid >> 5;
    const int warp_m = wid & 3;          // 4 x 16 rows
    const int warp_n = wid >> 2;         // 2 x 64 cols
    const int m0 = blockIdx.x * 64 + warp_m * 16;
    const int n0 = warp_n * 64;

    wmma::fragment<wmma::accumulator, 16, 16, 16, float> c[4];
    #pragma unroll
    for (int j = 0; j < 4; j++) wmma::fill_fragment(c[j], 0.0f);

    #pragma unroll
    for (int k0 = 0; k0 < 128; k0 += 16) {
        wmma::fragment<wmma::matrix_a, 16, 16, 16, __half, wmma::row_major> a;
        wmma::load_matrix_sync(a, g_y2h + (size_t)m0 * 128 + k0, 128);
        #pragma unroll
        for (int j = 0; j < 4; j++) {
            wmma::fragment<wmma::matrix_b, 16, 16, 16, __half, wmma::col_major> b;
            wmma::load_matrix_sync(b, g_wh + (size_t)(n0 + j * 16) * 128 + k0, 128);
            wmma::mma_sync(c[j], a, b, c[j]);
        }
    }

    // epilogue: per-warp smem staging -> fp16 z2
    #pragma unroll
    for (int j = 0; j < 4; j++) {
        wmma::store_matrix_sync(&s_c[wid][0], c[j], 16, wmma::mem_row_major);
        __syncwarp();
        const int r = lane >> 2;            // 0..7
        const int cb = (lane & 3) * 4;      // 0,4,8,12
        #pragma unroll
        for (int h = 0; h < 2; h++) {
            int row = r + h * 8;
            float* src = &s_c[wid][row * 16 + cb];
            __half2 h0 = __floats2half2_rn(src[0], src[1]);
            __half2 h1 = __floats2half2_rn(src[2], src[3]);
            uint2 o;
            o.x = *(uint32_t*)&h0;
            o.y = *(uint32_t*)&h1;
            int gcol = n0 + j * 16 + cb;
            ((uint2*)g_z2h)[((size_t)(m0 + row) * 128 + gcol) >> 2] = o;
        }
        __syncwarp();
    }
}

// ---------------------------------------------------------------------------
// K5 (R16 REWRITE): warp-per-node gather.
// out[n] = rsqrt(deg_n) * sum_{e ni n} z2h[e] + b.
// One warp owns one node: z2h row = 256B = one uint2 per lane. Warp privately
// loads its 256 bit-words (8/lane, coalesced), 1-warp scan + extraction into a
// private smem segment (fixed lane-major order -> deterministic), then gathers
// with 2 accumulators (fixed combine order). No __syncthreads, no cross-warp
// combine; 8 nodes/block, 2048 blocks.
// PERMUTED row bits: word wi, bit b -> edge (wi>>2)*128 + 4*b + (wi&3).
// ---------------------------------------------------------------------------
__global__ __launch_bounds__(256) void k_node_gather(const float* __restrict__ bvec,
                                                     float* __restrict__ out) {
    __shared__ int s_idx[8][256];        // per-warp private segment (deg<=256 safe)
    const int tid = threadIdx.x;
    const int lane = tid & 31, wid = tid >> 5;
    const int n = blockIdx.x * 8 + wid;
    const uint32_t* bits = g_bits_r + (size_t)n * WR;

    // load 8 words/lane (coalesced across the warp), count
    uint32_t w[8];
    int cnt = 0;
    #pragma unroll
    for (int k = 0; k < 8; k++) { w[k] = bits[lane + 32 * k]; cnt += __popc(w[k]); }

    // warp-exclusive scan of lane counts (lane-major list order: deterministic)
    int v = cnt;
    #pragma unroll
    for (int o = 1; o < 32; o <<= 1) {
        int t = __shfl_up_sync(0xffffffffu, v, o);
        if (lane >= o) v += t;
    }
    const int tot = __shfl_sync(0xffffffffu, v, 31);
    int pos = v - cnt;

    // extraction: lane's 8 words in k-order
    #pragma unroll
    for (int k = 0; k < 8; k++) {
        uint32_t ww = w[k];
        const int wi = lane + 32 * k;
        const int ebase = (wi >> 2) << 7;
        const int elow  = wi & 3;
        while (ww) { int b = __ffs(ww) - 1; ww &= ww - 1; s_idx[wid][pos++] = ebase + 4 * b + elow; }
    }
    __syncwarp();

    // gather: lane covers halves [4*lane, 4*lane+4) of each z2h row
    const uint2* __restrict__ Z = (const uint2*)g_z2h;
    float4 acc0 = make_float4(0.f, 0.f, 0.f, 0.f);
    float4 acc1 = make_float4(0.f, 0.f, 0.f, 0.f);
    int i = 0;
    for (; i + 1 < tot; i += 2) {
        int e0 = s_idx[wid][i], e1 = s_idx[wid][i + 1];
        uint2 ua = __ldg(&Z[(size_t)e0 * 32 + lane]);
        uint2 ub = __ldg(&Z[(size_t)e1 * 32 + lane]);
        float2 a0 = __half22float2(*(__half2*)&ua.x);
        float2 a1 = __half22float2(*(__half2*)&ua.y);
        float2 b0 = __half22float2(*(__half2*)&ub.x);
        float2 b1 = __half22float2(*(__half2*)&ub.y);
        acc0.x += a0.x; acc0.y += a0.y; acc0.z += a1.x; acc0.w += a1.y;
        acc1.x += b0.x; acc1.y += b0.y; acc1.z += b1.x; acc1.w += b1.y;
    }
    if (i < tot) {
        int e0 = s_idx[wid][i];
        uint2 ua = __ldg(&Z[(size_t)e0 * 32 + lane]);
        float2 a0 = __half22float2(*(__half2*)&ua.x);
        float2 a1 = __half22float2(*(__half2*)&ua.y);
        acc0.x += a0.x; acc0.y += a0.y; acc0.z += a1.x; acc0.w += a1.y;
    }
    // fixed combine order
    float4 r = make_float4(acc0.x + acc1.x, acc0.y + acc1.y,
                           acc0.z + acc1.z, acc0.w + acc1.w);
    float dv = (tot > 0) ? rsqrtf((float)tot) : 0.0f;
    float4 bb = ((const float4*)bvec)[lane];
    r.x = r.x * dv + bb.x; r.y = r.y * dv + bb.y;
    r.z = r.z * dv + bb.z; r.w = r.w * dv + bb.w;
    ((float4*)out)[(size_t)n * 32 + lane] = r;
}

// ---------------------------------------------------------------------------
extern "C" void kernel_launch(void* const* d_in, const int* in_sizes, int n_in,
                              void* d_out, int out_size) {
    const float* x = (const float*)d_in[0];   // [16384, 128]
    const float* H = (const float*)d_in[1];   // [16384, 8192]
    const float* W = (const float*)d_in[2];   // [128, 128]
    const float* b = (const float*)d_in[3];   // [128]
    float* out = (float*)d_out;               // [16384, 128]

    dim3 gp(NE / 256, NN / 256);              // 32 x 64 = 2048 CTAs (R12 exact)
    k_pack<<<gp, 256>>>(H);                   // idx 0
    k_finalize<<<NN, 128>>>(x, W);            // idx 1 (wconv fused)
    k_edge_gather<<<NE, 256>>>();             // idx 2
    k_gemm_wmma<<<NE / 64, 256>>>();          // idx 3  <- profiled (expect ~10.2us)
    k_node_gather<<<NN / 8, 256>>>(b, out);   // idx 4  (new: warp-per-node)
}